// round 2
// baseline (speedup 1.0000x reference)
#include <cuda_runtime.h>

typedef unsigned long long ull;

constexpr int N = 1024, T = 512, B = 128, NI = 6, NO = 2;
constexpr float ALPHA = 0.1f, GAMMA = 0.1f;
// sqrt(2/ALPHA) * 0.03
constexpr float NOISE_SCALE = 0.13416407864998738f;

constexpr int NBLK = 128;   // 64 row-tiles x 2 col-tiles (all co-resident on 148 SMs)
constexpr int NTHR = 256;
constexpr int RPB  = 16;    // rows per block
constexpr int CPB  = 64;    // batch cols per block

// states[t] is the state buffer for step t; 512*1024*128 fp32 = 256 MB scratch
__device__ float g_states[(size_t)T * N * B];
__device__ unsigned g_count;
__device__ volatile unsigned g_gen;

__device__ __forceinline__ ull pack2(float x) {
    ull r; asm("mov.b64 %0, {%1, %1};" : "=l"(r) : "f"(x)); return r;
}
__device__ __forceinline__ ull pack2f(float x, float y) {
    ull r; asm("mov.b64 %0, {%1, %2};" : "=l"(r) : "f"(x), "f"(y)); return r;
}
__device__ __forceinline__ float2 unpack2(ull v) {
    float2 r; asm("mov.b64 {%0, %1}, %2;" : "=f"(r.x), "=f"(r.y) : "l"(v)); return r;
}
__device__ __forceinline__ void ffma2(ull &acc, ull a, ull b) {
    asm("fma.rn.f32x2 %0, %1, %2, %0;" : "+l"(acc) : "l"(a), "l"(b));
}

// Sense-reversing grid barrier. Safe: 128 blocks, 1 block/SM (128KB smem), all resident.
__device__ __forceinline__ void grid_sync() {
    __syncthreads();
    if (threadIdx.x == 0) {
        unsigned gen = g_gen;           // volatile read BEFORE arriving
        __threadfence();                // release my states[t+1] writes
        if (atomicAdd(&g_count, 1u) == NBLK - 1) {
            g_count = 0;
            __threadfence();
            atomicAdd((unsigned*)&g_gen, 1u);
        } else {
            while (g_gen == gen) { __nanosleep(64); }
        }
        __threadfence();                // acquire other blocks' writes
    }
    __syncthreads();
}

__global__ void __launch_bounds__(NTHR, 1)
rnn_persistent_kernel(const float* __restrict__ u,
                      const float* __restrict__ rec_noise,
                      const float* __restrict__ inp_noise,
                      const float* __restrict__ W_rec,
                      const float* __restrict__ W_inp,
                      const float* __restrict__ y_init)
{
    extern __shared__ ull Wsh[];        // [RPB][N] W values, duplicated in both f32 lanes

    const int tid = threadIdx.x;
    const int rowTile = blockIdx.x >> 1;
    const int colTile = blockIdx.x & 1;
    const int r0 = rowTile * RPB;
    const int c0 = colTile * CPB;

    // thread map: 32 col-groups (2 cols each, packed as f32x2) x 8 row-pairs
    const int cg = tid & 31;
    const int rp = tid >> 5;
    const int c  = c0 + cg * 2;
    const int ra = r0 + rp * 2;
    const int rb = ra + 1;
    const int ch = c >> 1;              // index in 64-bit units within a row of B

    // One-time: load my 16 W_rec rows into smem, lane-duplicated for FFMA2
    for (int idx = tid; idx < RPB * N; idx += NTHR) {
        int r = idx >> 10;              // local row (N = 1024)
        int k = idx & (N - 1);
        Wsh[idx] = pack2(W_rec[(size_t)(r0 + r) * N + k]);
    }

    // One-time: input-projection weights for my two rows
    float wia[NI], wib[NI];
#pragma unroll
    for (int i = 0; i < NI; i++) {
        wia[i] = W_inp[ra * NI + i];
        wib[i] = W_inp[rb * NI + i];
    }

    // init states[0] = broadcast(y_init)
    {
        ull* S0 = (ull*)g_states;
        S0[ra * (B / 2) + ch] = pack2(y_init[ra]);
        S0[rb * (B / 2) + ch] = pack2(y_init[rb]);
    }
    grid_sync();

    const ull* Wa = &Wsh[(rp * 2 + 0) * N];
    const ull* Wb = &Wsh[(rp * 2 + 1) * N];

    for (int t = 0; t < T - 1; t++) {
        const ull* S = (const ull*)(g_states + (size_t)t * (N * B));
        ull* Snew    = (ull*)(g_states + (size_t)(t + 1) * (N * B));

        ull acc0 = 0ull, acc1 = 0ull;   // {0.f, 0.f}

#pragma unroll 4
        for (int k = 0; k < N; k += 4) {
            ull s0 = S[(k + 0) * (B / 2) + ch];
            ull s1 = S[(k + 1) * (B / 2) + ch];
            ull s2 = S[(k + 2) * (B / 2) + ch];
            ull s3 = S[(k + 3) * (B / 2) + ch];
            ulonglong2 wa01 = *(const ulonglong2*)&Wa[k];
            ulonglong2 wa23 = *(const ulonglong2*)&Wa[k + 2];
            ulonglong2 wb01 = *(const ulonglong2*)&Wb[k];
            ulonglong2 wb23 = *(const ulonglong2*)&Wb[k + 2];
            ffma2(acc0, wa01.x, s0); ffma2(acc0, wa01.y, s1);
            ffma2(acc0, wa23.x, s2); ffma2(acc0, wa23.y, s3);
            ffma2(acc1, wb01.x, s0); ffma2(acc1, wb01.y, s1);
            ffma2(acc1, wb23.x, s2); ffma2(acc1, wb23.y, s3);
        }

        float2 h0 = unpack2(acc0);
        float2 h1 = unpack2(acc1);

        // input projection: h += W_inp @ (u_t + inp_scale * inp_noise_t)
#pragma unroll
        for (int i = 0; i < NI; i++) {
            const size_t off = (size_t)i * T * B + (size_t)t * B + c;
            float2 uu = *(const float2*)&u[off];
            float2 nn = *(const float2*)&inp_noise[off];
            float xx = fmaf(NOISE_SCALE, nn.x, uu.x);
            float xy = fmaf(NOISE_SCALE, nn.y, uu.y);
            h0.x = fmaf(wia[i], xx, h0.x);  h0.y = fmaf(wia[i], xy, h0.y);
            h1.x = fmaf(wib[i], xx, h1.x);  h1.y = fmaf(wib[i], xy, h1.y);
        }

        // pointwise Euler update, rows ra/rb, my 2 cols
        {
            float2 so = unpack2(S[ra * (B / 2) + ch]);
            const size_t noff = (size_t)ra * T * B + (size_t)t * B + c;
            float2 rn = *(const float2*)&rec_noise[noff];
            float hx = fmaxf(h0.x, 0.0f), hy = fmaxf(h0.y, 0.0f);
            float nx = so.x + ALPHA * (-so.x + hx + NOISE_SCALE * rn.x - GAMMA * so.x * so.x * so.x);
            float ny = so.y + ALPHA * (-so.y + hy + NOISE_SCALE * rn.y - GAMMA * so.y * so.y * so.y);
            Snew[ra * (B / 2) + ch] = pack2f(nx, ny);
        }
        {
            float2 so = unpack2(S[rb * (B / 2) + ch]);
            const size_t noff = (size_t)rb * T * B + (size_t)t * B + c;
            float2 rn = *(const float2*)&rec_noise[noff];
            float hx = fmaxf(h1.x, 0.0f), hy = fmaxf(h1.y, 0.0f);
            float nx = so.x + ALPHA * (-so.x + hx + NOISE_SCALE * rn.x - GAMMA * so.x * so.x * so.x);
            float ny = so.y + ALPHA * (-so.y + hy + NOISE_SCALE * rn.y - GAMMA * so.y * so.y * so.y);
            Snew[rb * (B / 2) + ch] = pack2f(nx, ny);
        }

        grid_sync();
    }
}

// outputs[o, t, c] = sum_r W_out[o, r] * states[t, r, c]
__global__ void __launch_bounds__(128)
readout_kernel(const float* __restrict__ W_out, float* __restrict__ out)
{
    __shared__ float wsh[NO * N];
    const int t = blockIdx.x;
    for (int i = threadIdx.x; i < NO * N; i += 128) wsh[i] = W_out[i];
    __syncthreads();

    const int cidx = threadIdx.x;
    const float* S = g_states + (size_t)t * (N * B);
    float a0 = 0.0f, a1 = 0.0f;
#pragma unroll 8
    for (int r = 0; r < N; r++) {
        float s = S[r * B + cidx];
        a0 = fmaf(wsh[r], s, a0);
        a1 = fmaf(wsh[N + r], s, a1);
    }
    out[(size_t)t * B + cidx] = a0;
    out[(size_t)T * B + (size_t)t * B + cidx] = a1;
}

extern "C" void kernel_launch(void* const* d_in, const int* in_sizes, int n_in,
                              void* d_out, int out_size)
{
    const float* u         = (const float*)d_in[0];
    const float* rec_noise = (const float*)d_in[1];
    const float* inp_noise = (const float*)d_in[2];
    const float* W_rec     = (const float*)d_in[3];
    const float* W_inp     = (const float*)d_in[4];
    const float* W_out     = (const float*)d_in[5];
    const float* y_init    = (const float*)d_in[6];
    float* out = (float*)d_out;

    const size_t smem = (size_t)RPB * N * sizeof(ull);  // 128 KB
    cudaFuncSetAttribute(rnn_persistent_kernel,
                         cudaFuncAttributeMaxDynamicSharedMemorySize, (int)smem);

    rnn_persistent_kernel<<<NBLK, NTHR, smem>>>(u, rec_noise, inp_noise,
                                                W_rec, W_inp, y_init);
    readout_kernel<<<T, 128>>>(W_out, out);
}

// round 4
// speedup vs baseline: 1.3119x; 1.3119x over previous
#include <cuda_runtime.h>

typedef unsigned long long ull;

constexpr int N = 1024, T = 512, B = 128, NI = 6, NO = 2;
constexpr float ALPHA = 0.1f, GAMMA = 0.1f;
constexpr float NOISE_SCALE = 0.13416407864998738f;   // sqrt(2/0.1)*0.03

constexpr int NBLK = 128;    // 64 row-tiles x 2 col-tiles, all co-resident
constexpr int NTHR = 256;
constexpr int RPB  = 16;     // rows per block
constexpr int CPB  = 64;     // batch cols per block
constexpr int CHUNK = 128;   // k rows staged per chunk
constexpr int NCHUNK = N / CHUNK;  // 8
constexpr int NSTAGE = 3;    // smem staging buffers

__device__ float g_states[(size_t)T * N * B];   // 256 MB scratch
__device__ unsigned g_count;
__device__ volatile unsigned g_gen;

__device__ __forceinline__ ull pack2(float x) {
    ull r; asm("mov.b64 %0, {%1, %1};" : "=l"(r) : "f"(x)); return r;
}
__device__ __forceinline__ float2 unpack2(ull v) {
    float2 r; asm("mov.b64 {%0, %1}, %2;" : "=f"(r.x), "=f"(r.y) : "l"(v)); return r;
}
__device__ __forceinline__ void ffma2(ull &acc, ull a, ull b) {
    asm("fma.rn.f32x2 %0, %1, %2, %0;" : "+l"(acc) : "l"(a), "l"(b));
}
__device__ __forceinline__ void cp_async16(unsigned dst, const void* src) {
    asm volatile("cp.async.cg.shared.global [%0], [%1], 16;" :: "r"(dst), "l"(src));
}
__device__ __forceinline__ void cp_commit() {
    asm volatile("cp.async.commit_group;");
}
template<int n> __device__ __forceinline__ void cp_wait() {
    asm volatile("cp.async.wait_group %0;" :: "n"(n));
}

// Sense-reversing grid barrier (128 blocks, 1/SM guaranteed by 224KB smem)
__device__ __forceinline__ void grid_sync() {
    __syncthreads();
    if (threadIdx.x == 0) {
        unsigned gen = g_gen;
        __threadfence();
        if (atomicAdd(&g_count, 1u) == NBLK - 1) {
            g_count = 0;
            __threadfence();
            atomicAdd((unsigned*)&g_gen, 1u);
        } else {
            while (g_gen == gen) { __nanosleep(32); }
        }
        __threadfence();
    }
    __syncthreads();
}

__global__ void __launch_bounds__(NTHR, 1)
rnn_persistent_kernel(const float* __restrict__ u,
                      const float* __restrict__ rec_noise,
                      const float* __restrict__ inp_noise,
                      const float* __restrict__ W_rec,
                      const float* __restrict__ W_inp,
                      const float* __restrict__ y_init)
{
    extern __shared__ char smraw[];
    ull*   Wsh = (ull*)smraw;                                   // [RPB][N], lane-dup
    float* Sst = (float*)(smraw + (size_t)RPB * N * sizeof(ull)); // [NSTAGE][CHUNK*CPB]

    const int tid = threadIdx.x;
    const int rowTile = blockIdx.x >> 1;
    const int colTile = blockIdx.x & 1;
    const int r0 = rowTile * RPB;
    const int c0 = colTile * CPB;

    const int cg = tid & 31;          // col-pair index (2 cols)
    const int tg = tid >> 5;          // row-group (2 rows)
    const int c  = c0 + cg * 2;
    const int la = tg * 2, lb = la + 1;
    const int ra = r0 + la, rb = r0 + lb;

    // One-time: W_rec rows into smem, lane-duplicated for FFMA2
    for (int idx = tid; idx < RPB * N; idx += NTHR) {
        int r = idx >> 10;
        int k = idx & (N - 1);
        Wsh[idx] = pack2(W_rec[(size_t)(r0 + r) * N + k]);
    }

    float wia[NI], wib[NI];
#pragma unroll
    for (int i = 0; i < NI; i++) {
        wia[i] = W_inp[ra * NI + i];
        wib[i] = W_inp[rb * NI + i];
    }

    // states[0] = broadcast(y_init)
    {
        float ya = y_init[ra], yb = y_init[rb];
        *(float2*)&g_states[(size_t)ra * B + c] = make_float2(ya, ya);
        *(float2*)&g_states[(size_t)rb * B + c] = make_float2(yb, yb);
    }
    grid_sync();

    const ulonglong2* Wa = (const ulonglong2*)&Wsh[la * N];
    const ulonglong2* Wb = (const ulonglong2*)&Wsh[lb * N];
    unsigned sbase = (unsigned)__cvta_generic_to_shared(Sst);

    for (int t = 0; t < T - 1; t++) {
        const float* Sold = g_states + (size_t)t * (N * B);
        float*       Snew = g_states + (size_t)(t + 1) * (N * B);

        // stage chunk ch of Sold[ch*128 .. +128, c0 .. c0+64] into buffer ch%3
        auto issue = [&](int ch) {
            unsigned bufoff = (unsigned)((ch % NSTAGE) * (CHUNK * CPB * 4));
#pragma unroll
            for (int j = 0; j < 8; j++) {
                int f  = tid + j * NTHR;     // 0..2047 float4 of the chunk
                int kk = f >> 4;
                int cc = f & 15;
                cp_async16(sbase + bufoff + (unsigned)f * 16,
                           Sold + (size_t)(ch * CHUNK + kk) * B + c0 + cc * 4);
            }
            cp_commit();
        };

        issue(0);
        issue(1);

        ull acc0 = 0ull, acc1 = 0ull;

        for (int ch = 0; ch < NCHUNK; ch++) {
            if (ch < NCHUNK - 1) cp_wait<1>(); else cp_wait<0>();
            __syncthreads();
            if (ch + 2 < NCHUNK) issue(ch + 2);

            const ull* Sp = (const ull*)(Sst + (ch % NSTAGE) * (CHUNK * CPB)) + cg;
            const ulonglong2* Wap = Wa + (ch * CHUNK >> 1);
            const ulonglong2* Wbp = Wb + (ch * CHUNK >> 1);

#pragma unroll 4
            for (int kk = 0; kk < CHUNK; kk += 2) {
                ull s0 = Sp[(kk + 0) * 32];
                ull s1 = Sp[(kk + 1) * 32];
                ulonglong2 wa = Wap[kk >> 1];
                ulonglong2 wb = Wbp[kk >> 1];
                ffma2(acc0, wa.x, s0); ffma2(acc0, wa.y, s1);
                ffma2(acc1, wb.x, s0); ffma2(acc1, wb.y, s1);
            }
        }

        float2 h0 = unpack2(acc0);
        float2 h1 = unpack2(acc1);

        // input projection
#pragma unroll
        for (int i = 0; i < NI; i++) {
            const size_t off = (size_t)i * T * B + (size_t)t * B + c;
            float2 uu = *(const float2*)&u[off];
            float2 nn = *(const float2*)&inp_noise[off];
            float xx = fmaf(NOISE_SCALE, nn.x, uu.x);
            float xy = fmaf(NOISE_SCALE, nn.y, uu.y);
            h0.x = fmaf(wia[i], xx, h0.x);  h0.y = fmaf(wia[i], xy, h0.y);
            h1.x = fmaf(wib[i], xx, h1.x);  h1.y = fmaf(wib[i], xy, h1.y);
        }

        // pointwise Euler update
        {
            float2 so = *(const float2*)&Sold[(size_t)ra * B + c];
            const size_t noff = (size_t)ra * T * B + (size_t)t * B + c;
            float2 rn = *(const float2*)&rec_noise[noff];
            float hx = fmaxf(h0.x, 0.0f), hy = fmaxf(h0.y, 0.0f);
            float nx = so.x + ALPHA * (-so.x + hx + NOISE_SCALE * rn.x - GAMMA * so.x * so.x * so.x);
            float ny = so.y + ALPHA * (-so.y + hy + NOISE_SCALE * rn.y - GAMMA * so.y * so.y * so.y);
            *(float2*)&Snew[(size_t)ra * B + c] = make_float2(nx, ny);
        }
        {
            float2 so = *(const float2*)&Sold[(size_t)rb * B + c];
            const size_t noff = (size_t)rb * T * B + (size_t)t * B + c;
            float2 rn = *(const float2*)&rec_noise[noff];
            float hx = fmaxf(h1.x, 0.0f), hy = fmaxf(h1.y, 0.0f);
            float nx = so.x + ALPHA * (-so.x + hx + NOISE_SCALE * rn.x - GAMMA * so.x * so.x * so.x);
            float ny = so.y + ALPHA * (-so.y + hy + NOISE_SCALE * rn.y - GAMMA * so.y * so.y * so.y);
            *(float2*)&Snew[(size_t)rb * B + c] = make_float2(nx, ny);
        }

        grid_sync();
    }
}

// outputs[o, t, c] = sum_r W_out[o, r] * states[t, r, c]
__global__ void __launch_bounds__(128)
readout_kernel(const float* __restrict__ W_out, float* __restrict__ out)
{
    __shared__ float wsh[NO * N];
    const int t = blockIdx.x;
    for (int i = threadIdx.x; i < NO * N; i += 128) wsh[i] = W_out[i];
    __syncthreads();

    const int cidx = threadIdx.x;
    const float* S = g_states + (size_t)t * (N * B);
    float a0 = 0.0f, a1 = 0.0f;
#pragma unroll 8
    for (int r = 0; r < N; r++) {
        float s = S[r * B + cidx];
        a0 = fmaf(wsh[r], s, a0);
        a1 = fmaf(wsh[N + r], s, a1);
    }
    out[(size_t)t * B + cidx] = a0;
    out[(size_t)T * B + (size_t)t * B + cidx] = a1;
}

extern "C" void kernel_launch(void* const* d_in, const int* in_sizes, int n_in,
                              void* d_out, int out_size)
{
    const float* u         = (const float*)d_in[0];
    const float* rec_noise = (const float*)d_in[1];
    const float* inp_noise = (const float*)d_in[2];
    const float* W_rec     = (const float*)d_in[3];
    const float* W_inp     = (const float*)d_in[4];
    const float* W_out     = (const float*)d_in[5];
    const float* y_init    = (const float*)d_in[6];
    float* out = (float*)d_out;

    const size_t smem = (size_t)RPB * N * sizeof(ull)
                      + (size_t)NSTAGE * CHUNK * CPB * sizeof(float);  // 224 KB
    cudaFuncSetAttribute(rnn_persistent_kernel,
                         cudaFuncAttributeMaxDynamicSharedMemorySize, (int)smem);

    rnn_persistent_kernel<<<NBLK, NTHR, smem>>>(u, rec_noise, inp_noise,
                                                W_rec, W_inp, y_init);
    readout_kernel<<<T, 128>>>(W_out, out);
}

// round 6
// speedup vs baseline: 2.1808x; 1.6624x over previous
#include <cuda_runtime.h>

typedef unsigned long long ull;

constexpr int N = 1024, T = 512, B = 128, NI = 6, NO = 2;
constexpr float ALPHA = 0.1f, GAMMA = 0.1f;
constexpr float NOISE_SCALE = 0.13416407864998738f;   // sqrt(2/0.1)*0.03

constexpr int NBLK = 128;     // 64 row-tiles x 2 col-tiles, all co-resident
constexpr int NTHR = 256;
constexpr int RPB  = 16;      // rows per block
constexpr int CPB  = 64;      // batch cols per block
constexpr int KSPLIT = 8;     // one warp per k-range
constexpr int KRANGE = N / KSPLIT;    // 128
constexpr int SLABK  = 16;            // k rows per staged slab
constexpr int NSLAB  = KRANGE / SLABK; // 8

constexpr size_t W_BYTES = (size_t)RPB * N * sizeof(ull);          // 128 KB
constexpr size_t STAGE_BYTES = (size_t)KSPLIT * 2 * SLABK * CPB * 4; // 64 KB
constexpr size_t SMEM_TOTAL = W_BYTES + STAGE_BYTES;               // 192 KB

__device__ float g_states[(size_t)T * N * B];   // 256 MB scratch
__device__ unsigned g_count;
__device__ volatile unsigned g_gen;

__device__ __forceinline__ ull pack2(float x) {
    ull r; asm("mov.b64 %0, {%1, %1};" : "=l"(r) : "f"(x)); return r;
}
__device__ __forceinline__ float2 unpack2(ull v) {
    float2 r; asm("mov.b64 {%0, %1}, %2;" : "=f"(r.x), "=f"(r.y) : "l"(v)); return r;
}
__device__ __forceinline__ void ffma2(ull &acc, ull a, ull b) {
    asm("fma.rn.f32x2 %0, %1, %2, %0;" : "+l"(acc) : "l"(a), "l"(b));
}
__device__ __forceinline__ void cp_async16(unsigned dst, const void* src) {
    asm volatile("cp.async.cg.shared.global [%0], [%1], 16;" :: "r"(dst), "l"(src));
}
__device__ __forceinline__ void cp_commit() {
    asm volatile("cp.async.commit_group;");
}
template<int n> __device__ __forceinline__ void cp_wait() {
    asm volatile("cp.async.wait_group %0;" :: "n"(n));
}

// Sense-reversing grid barrier (128 blocks, 1/SM guaranteed by 192KB smem)
__device__ __forceinline__ void grid_sync() {
    __syncthreads();
    if (threadIdx.x == 0) {
        unsigned gen = g_gen;
        __threadfence();
        if (atomicAdd(&g_count, 1u) == NBLK - 1) {
            g_count = 0;
            __threadfence();
            atomicAdd((unsigned*)&g_gen, 1u);
        } else {
            while (g_gen == gen) { __nanosleep(32); }
        }
        __threadfence();
    }
    __syncthreads();
}

__global__ void __launch_bounds__(NTHR, 1)
rnn_persistent_kernel(const float* __restrict__ u,
                      const float* __restrict__ rec_noise,
                      const float* __restrict__ inp_noise,
                      const float* __restrict__ W_rec,
                      const float* __restrict__ W_inp,
                      const float* __restrict__ y_init)
{
    extern __shared__ char smraw[];
    ull*   Wsh   = (ull*)smraw;                   // [RPB][N] lane-duplicated
    float* Stage = (float*)(smraw + W_BYTES);     // [KSPLIT][2][SLABK][CPB]
    ull*   Red   = (ull*)(smraw + W_BYTES);       // aliased after mainloop

    const int tid = threadIdx.x;
    const int w   = tid >> 5;          // warp = k-range owner
    const int l   = tid & 31;
    const int rg  = l >> 4;            // row-group: rows rg*8 .. +8 (local)
    const int cgr = l & 15;            // col-group: cols cgr*4 .. +3 (local)

    const int rowTile = blockIdx.x >> 1;
    const int colTile = blockIdx.x & 1;
    const int r0 = rowTile * RPB;
    const int c0 = colTile * CPB;

    // epilogue mapping (2 rows x 2 cols per thread)
    const int erp = tid >> 5;                 // row-pair 0..7
    const int ep  = tid & 31;                 // col-pair 0..31
    const int lra = erp * 2, lrb = lra + 1;   // local rows
    const int ra  = r0 + lra, rb = r0 + lrb;  // global rows
    const int ec  = c0 + ep * 2;              // global col

    // one-time: W_rec rows into smem, lane-duplicated
    for (int idx = tid; idx < RPB * N; idx += NTHR) {
        int r = idx >> 10;
        int k = idx & (N - 1);
        Wsh[idx] = pack2(W_rec[(size_t)(r0 + r) * N + k]);
    }

    float wia[NI], wib[NI];
#pragma unroll
    for (int i = 0; i < NI; i++) {
        wia[i] = W_inp[ra * NI + i];
        wib[i] = W_inp[rb * NI + i];
    }

    // states[0] = broadcast(y_init)
    {
        float ya = y_init[ra], yb = y_init[rb];
        *(float2*)&g_states[(size_t)ra * B + ec] = make_float2(ya, ya);
        *(float2*)&g_states[(size_t)rb * B + ec] = make_float2(yb, yb);
    }
    grid_sync();

    const unsigned stage_base =
        (unsigned)__cvta_generic_to_shared(Stage) + (unsigned)(w * 2 * SLABK * CPB * 4);

    for (int t = 0; t < T - 1; t++) {
        const float* Sold = g_states + (size_t)t * (N * B);
        float*       Snew = g_states + (size_t)(t + 1) * (N * B);

        // stage slab s (16 k-rows x 64 cols) of my k-range into my buffer (s&1)
        auto issue = [&](int s) {
            const int k0 = w * KRANGE + s * SLABK;
            const unsigned dst = stage_base + (unsigned)((s & 1) * (SLABK * CPB * 4));
            const float* src0 = Sold + (size_t)k0 * B + c0;
#pragma unroll
            for (int j = 0; j < 8; j++) {
                int f  = j * 32 + l;         // 0..255 float4 of the slab
                int kk = f >> 4;
                int cc = f & 15;
                cp_async16(dst + (unsigned)f * 16, src0 + (size_t)kk * B + cc * 4);
            }
            cp_commit();
        };

        issue(0);
        issue(1);

        ull acc[8][2];
#pragma unroll
        for (int rr = 0; rr < 8; rr++) { acc[rr][0] = 0ull; acc[rr][1] = 0ull; }

        for (int s = 0; s < NSLAB; s++) {
            if (s < NSLAB - 1) cp_wait<1>(); else cp_wait<0>();
            __syncwarp();

            const float* Sp = Stage + (w * 2 + (s & 1)) * (SLABK * CPB) + cgr * 4;
            const int kg0 = w * KRANGE + s * SLABK;

#pragma unroll
            for (int kk = 0; kk < SLABK; kk += 2) {
                ulonglong2 sv0 = *(const ulonglong2*)(Sp + (kk + 0) * CPB);
                ulonglong2 sv1 = *(const ulonglong2*)(Sp + (kk + 1) * CPB);
#pragma unroll
                for (int rr = 0; rr < 8; rr++) {
                    ulonglong2 wv = *(const ulonglong2*)&Wsh[(size_t)(rg * 8 + rr) * N + kg0 + kk];
                    ffma2(acc[rr][0], wv.x, sv0.x);
                    ffma2(acc[rr][1], wv.x, sv0.y);
                    ffma2(acc[rr][0], wv.y, sv1.x);
                    ffma2(acc[rr][1], wv.y, sv1.y);
                }
            }

            if (s + 2 < NSLAB) { __syncwarp(); issue(s + 2); }
        }

        // cross-warp k-reduction through smem (aliases stage region)
        __syncthreads();
        {
            ulonglong2* dst = (ulonglong2*)&Red[(size_t)(w * 32 + l) * 16];
#pragma unroll
            for (int rr = 0; rr < 8; rr++) {
                ulonglong2 v; v.x = acc[rr][0]; v.y = acc[rr][1];
                dst[rr] = v;
            }
        }
        __syncthreads();

        // epilogue thread: sum 8 partials for 2 rows x 1 col-pair
        float2 h0 = make_float2(0.f, 0.f), h1 = make_float2(0.f, 0.f);
        {
            const int lane_a = (lra >> 3) * 16 + (ep >> 1);
            const int lane_b = (lrb >> 3) * 16 + (ep >> 1);
            const int ia = (lra & 7) * 2 + (ep & 1);
            const int ib = (lrb & 7) * 2 + (ep & 1);
#pragma unroll
            for (int wj = 0; wj < KSPLIT; wj++) {
                float2 fa = unpack2(Red[(size_t)(wj * 32 + lane_a) * 16 + ia]);
                float2 fb = unpack2(Red[(size_t)(wj * 32 + lane_b) * 16 + ib]);
                h0.x += fa.x; h0.y += fa.y;
                h1.x += fb.x; h1.y += fb.y;
            }
        }

        // input projection
#pragma unroll
        for (int i = 0; i < NI; i++) {
            const size_t off = (size_t)i * T * B + (size_t)t * B + ec;
            float2 uu = *(const float2*)&u[off];
            float2 nn = *(const float2*)&inp_noise[off];
            float xx = fmaf(NOISE_SCALE, nn.x, uu.x);
            float xy = fmaf(NOISE_SCALE, nn.y, uu.y);
            h0.x = fmaf(wia[i], xx, h0.x);  h0.y = fmaf(wia[i], xy, h0.y);
            h1.x = fmaf(wib[i], xx, h1.x);  h1.y = fmaf(wib[i], xy, h1.y);
        }

        // pointwise Euler update
        {
            float2 so = *(const float2*)&Sold[(size_t)ra * B + ec];
            const size_t noff = (size_t)ra * T * B + (size_t)t * B + ec;
            float2 rn = *(const float2*)&rec_noise[noff];
            float hx = fmaxf(h0.x, 0.0f), hy = fmaxf(h0.y, 0.0f);
            float nx = so.x + ALPHA * (-so.x + hx + NOISE_SCALE * rn.x - GAMMA * so.x * so.x * so.x);
            float ny = so.y + ALPHA * (-so.y + hy + NOISE_SCALE * rn.y - GAMMA * so.y * so.y * so.y);
            *(float2*)&Snew[(size_t)ra * B + ec] = make_float2(nx, ny);
        }
        {
            float2 so = *(const float2*)&Sold[(size_t)rb * B + ec];
            const size_t noff = (size_t)rb * T * B + (size_t)t * B + ec;
            float2 rn = *(const float2*)&rec_noise[noff];
            float hx = fmaxf(h1.x, 0.0f), hy = fmaxf(h1.y, 0.0f);
            float nx = so.x + ALPHA * (-so.x + hx + NOISE_SCALE * rn.x - GAMMA * so.x * so.x * so.x);
            float ny = so.y + ALPHA * (-so.y + hy + NOISE_SCALE * rn.y - GAMMA * so.y * so.y * so.y);
            *(float2*)&Snew[(size_t)rb * B + ec] = make_float2(nx, ny);
        }

        grid_sync();   // also protects Red/Stage alias across steps
    }
}

// outputs[o, t, c] = sum_r W_out[o, r] * states[t, r, c]
// 256 threads: 2 row-halves x 128 cols, smem reduce.
__global__ void __launch_bounds__(256)
readout_kernel(const float* __restrict__ W_out, float* __restrict__ out)
{
    __shared__ float wsh[NO * N];
    __shared__ float part[2][2][B];    // [half][o][col]
    const int t = blockIdx.x;
    for (int i = threadIdx.x; i < NO * N; i += 256) wsh[i] = W_out[i];
    __syncthreads();

    const int half = threadIdx.x >> 7;
    const int cidx = threadIdx.x & 127;
    const float* S = g_states + (size_t)t * (N * B) + (size_t)half * (N / 2) * B;
    const float* w0 = wsh + half * (N / 2);
    float a0 = 0.0f, a1 = 0.0f;
#pragma unroll 8
    for (int r = 0; r < N / 2; r++) {
        float s = S[r * B + cidx];
        a0 = fmaf(w0[r], s, a0);
        a1 = fmaf(w0[N + r], s, a1);
    }
    part[half][0][cidx] = a0;
    part[half][1][cidx] = a1;
    __syncthreads();
    if (half == 0) {
        out[(size_t)t * B + cidx] = part[0][0][cidx] + part[1][0][cidx];
        out[(size_t)T * B + (size_t)t * B + cidx] = part[0][1][cidx] + part[1][1][cidx];
    }
}

extern "C" void kernel_launch(void* const* d_in, const int* in_sizes, int n_in,
                              void* d_out, int out_size)
{
    const float* u         = (const float*)d_in[0];
    const float* rec_noise = (const float*)d_in[1];
    const float* inp_noise = (const float*)d_in[2];
    const float* W_rec     = (const float*)d_in[3];
    const float* W_inp     = (const float*)d_in[4];
    const float* W_out     = (const float*)d_in[5];
    const float* y_init    = (const float*)d_in[6];
    float* out = (float*)d_out;

    cudaFuncSetAttribute(rnn_persistent_kernel,
                         cudaFuncAttributeMaxDynamicSharedMemorySize, (int)SMEM_TOTAL);

    rnn_persistent_kernel<<<NBLK, NTHR, SMEM_TOTAL>>>(u, rec_noise, inp_noise,
                                                      W_rec, W_inp, y_init);
    readout_kernel<<<T, 256>>>(W_out, out);
}